// round 11
// baseline (speedup 1.0000x reference)
#include <cuda_runtime.h>

#define NTOK 4096
#define CDIM 768
#define C3   2304
#define TPL  16
#define NH   12
#define HD   64

// __device__ scratch
__device__ float g_wq_hi[C3 * CDIM];
__device__ float g_wq_lo[C3 * CDIM];
__device__ float g_pw_hi[CDIM * CDIM];
__device__ float g_pw_lo[CDIM * CDIM];
__device__ float g_x_tf[NTOK * CDIM];     // tf32-rounded x
__device__ float g_qkv[NTOK * C3];        // Q (scaled+rounded), K,V (rounded)
__device__ float g_vT[NH * HD * NTOK];    // V^T per head, keys PERMUTED (see k_vT)
__device__ float g_att[NTOK * CDIM];      // rounded attention output

#define QSCALE (0.125f * 1.4426950408889634f)   // hd^-0.5 * log2(e)

// ---------------------------------------------------------------------------
// helpers
// ---------------------------------------------------------------------------
__device__ __forceinline__ unsigned f2tf(float x) {
    unsigned r;
    asm("cvt.rna.tf32.f32 %0, %1;" : "=r"(r) : "f"(x));
    return r;
}
__device__ __forceinline__ float f2tff(float x) { return __uint_as_float(f2tf(x)); }
__device__ __forceinline__ float ex2f(float x) {
    float y;
    asm("ex2.approx.f32 %0, %1;" : "=f"(y) : "f"(x));
    return y;
}
__device__ __forceinline__ void ldsm4(unsigned& r0, unsigned& r1, unsigned& r2, unsigned& r3,
                                      unsigned addr) {
    asm volatile("ldmatrix.sync.aligned.m8n8.x4.shared.b16 {%0,%1,%2,%3}, [%4];"
                 : "=r"(r0), "=r"(r1), "=r"(r2), "=r"(r3) : "r"(addr));
}
__device__ __forceinline__ void mma_tf32(float* d, const unsigned* a, unsigned b0, unsigned b1) {
    asm volatile(
        "mma.sync.aligned.m16n8k8.row.col.f32.tf32.tf32.f32 "
        "{%0,%1,%2,%3},{%4,%5,%6,%7},{%8,%9},{%0,%1,%2,%3};"
        : "+f"(d[0]), "+f"(d[1]), "+f"(d[2]), "+f"(d[3])
        : "r"(a[0]), "r"(a[1]), "r"(a[2]), "r"(a[3]), "r"(b0), "r"(b1));
}
__device__ __forceinline__ unsigned smem_u32(const void* p) {
    return (unsigned)__cvta_generic_to_shared(p);
}
__device__ __forceinline__ void cpasync16(unsigned dst, const void* src) {
    asm volatile("cp.async.cg.shared.global [%0], [%1], 16;" :: "r"(dst), "l"(src));
}

// ---------------------------------------------------------------------------
// K1 (merged prologue): template reduce -> split wq | split pw | round x.
// ---------------------------------------------------------------------------
#define NB_W  1728
#define NB_PW 576
#define NB_X  3072
__global__ void k_prologue(const float* __restrict__ tpl, const float* __restrict__ coef,
                           const float* __restrict__ pw, const float* __restrict__ x) {
    int b = blockIdx.x;
    if (b < NB_W) {
        __shared__ float w[TPL];
        if (threadIdx.x < TPL)
            w[threadIdx.x] = 0.5f * (coef[threadIdx.x] + coef[TPL + threadIdx.x]);
        __syncthreads();
        const int TOT = C3 * CDIM / 4;
        int idx = b * 256 + threadIdx.x;
        if (idx >= TOT) return;
        const float4* t4 = (const float4*)tpl;
        float4 acc = make_float4(0.f, 0.f, 0.f, 0.f);
#pragma unroll
        for (int t = 0; t < TPL; t++) {
            float4 v = t4[(size_t)t * TOT + idx];
            float wt = w[t];
            acc.x = fmaf(wt, v.x, acc.x);
            acc.y = fmaf(wt, v.y, acc.y);
            acc.z = fmaf(wt, v.z, acc.z);
            acc.w = fmaf(wt, v.w, acc.w);
        }
        float4 hi, lo;
        hi.x = f2tff(acc.x); lo.x = f2tff(acc.x - hi.x);
        hi.y = f2tff(acc.y); lo.y = f2tff(acc.y - hi.y);
        hi.z = f2tff(acc.z); lo.z = f2tff(acc.z - hi.z);
        hi.w = f2tff(acc.w); lo.w = f2tff(acc.w - hi.w);
        ((float4*)g_wq_hi)[idx] = hi;
        ((float4*)g_wq_lo)[idx] = lo;
    } else if (b < NB_W + NB_PW) {
        int idx = (b - NB_W) * 256 + threadIdx.x;
        if (idx >= CDIM * CDIM / 4) return;
        float4 v = ((const float4*)pw)[idx];
        float4 hi, lo;
        hi.x = f2tff(v.x); lo.x = f2tff(v.x - hi.x);
        hi.y = f2tff(v.y); lo.y = f2tff(v.y - hi.y);
        hi.z = f2tff(v.z); lo.z = f2tff(v.z - hi.z);
        hi.w = f2tff(v.w); lo.w = f2tff(v.w - hi.w);
        ((float4*)g_pw_hi)[idx] = hi;
        ((float4*)g_pw_lo)[idx] = lo;
    } else {
        int idx = (b - NB_W - NB_PW) * 256 + threadIdx.x;
        if (idx >= NTOK * CDIM / 4) return;
        float4 v = ((const float4*)x)[idx];
        v.x = f2tff(v.x); v.y = f2tff(v.y); v.z = f2tff(v.z); v.w = f2tff(v.w);
        ((float4*)g_x_tf)[idx] = v;
    }
}

// ---------------------------------------------------------------------------
// x2-split GEMM (TN): Y = A @ (Bhi+Blo)^T + bias.  A pre-rounded tf32.
// cp.async double-buffered, ONE __syncthreads per iteration.
// ---------------------------------------------------------------------------
#define GTILE 2560               // 128*20 floats
__device__ __forceinline__ void gemm_x2(const float* __restrict__ A,
                                        const float* __restrict__ Bhi,
                                        const float* __restrict__ Blo,
                                        const float* __restrict__ bias,
                                        float* __restrict__ Y,
                                        int Nd, int K, int mode, float* sm) {
    float* As = sm;
    float* Bh = sm + 2 * GTILE;
    float* Bl = sm + 4 * GTILE;

    int tid = threadIdx.x;
    int lane = tid & 31;
    int w = tid >> 5;
    int wm = w >> 1, wn = w & 1;
    int g = lane >> 2, q = lane & 3;
    int m0 = blockIdx.y * 128;
    int n0 = blockIdx.x * 128;

    float acc[2][8][4];
#pragma unroll
    for (int mi = 0; mi < 2; mi++)
#pragma unroll
        for (int nt = 0; nt < 8; nt++)
#pragma unroll
            for (int e = 0; e < 4; e++) acc[mi][nt][e] = 0.f;

    int row0 = tid >> 2, qc = tid & 3;
    int row1 = row0 + 64;
    unsigned asB = smem_u32(As), bhB = smem_u32(Bh), blB = smem_u32(Bl);
    unsigned st0 = (row0 * 20 + 4 * qc) << 2;
    unsigned st1 = (row1 * 20 + 4 * qc) << 2;
    const unsigned BUFB = GTILE * 4;

    int roffA = ((lane >> 3) & 1) * 8 + (lane & 7);
    int coffA = (lane >> 4) * 4;
    int roffB = ((lane >> 4) & 1) * 8 + (lane & 7);
    int coffB = ((lane >> 3) & 1) * 4;
    unsigned aOff = ((32 * wm + roffA) * 20 + coffA) << 2;
    unsigned bOff = ((64 * wn + roffB) * 20 + coffB) << 2;

    const float* aR0 = A + (size_t)(m0 + row0) * K + 4 * qc;
    const float* aR1 = A + (size_t)(m0 + row1) * K + 4 * qc;
    const float* bhR0 = Bhi + (size_t)(n0 + row0) * K + 4 * qc;
    const float* bhR1 = Bhi + (size_t)(n0 + row1) * K + 4 * qc;
    const float* blR0 = Blo + (size_t)(n0 + row0) * K + 4 * qc;
    const float* blR1 = Blo + (size_t)(n0 + row1) * K + 4 * qc;

    const int NT = K >> 4;

#define STAGE_ITER(itx, bufx)                                             \
    {                                                                     \
        int kk = (itx) << 4;                                              \
        unsigned bo = (bufx) * BUFB;                                      \
        cpasync16(asB + bo + st0, aR0 + kk);                              \
        cpasync16(asB + bo + st1, aR1 + kk);                              \
        cpasync16(bhB + bo + st0, bhR0 + kk);                             \
        cpasync16(bhB + bo + st1, bhR1 + kk);                             \
        cpasync16(blB + bo + st0, blR0 + kk);                             \
        cpasync16(blB + bo + st1, blR1 + kk);                             \
        asm volatile("cp.async.commit_group;");                           \
    }

    STAGE_ITER(0, 0)

    for (int it = 0; it < NT; it++) {
        int buf = it & 1;
        asm volatile("cp.async.wait_group 0;");
        __syncthreads();
        if (it + 1 < NT) STAGE_ITER(it + 1, buf ^ 1)

        unsigned aA = asB + buf * BUFB + aOff;
        unsigned bH = bhB + buf * BUFB + bOff;
        unsigned bL = blB + buf * BUFB + bOff;
#pragma unroll
        for (int ks = 0; ks < 2; ks++) {
            unsigned a0[4], a1[4];
            ldsm4(a0[0], a0[1], a0[2], a0[3], aA + ks * 32);
            ldsm4(a1[0], a1[1], a1[2], a1[3], aA + 16 * 20 * 4 + ks * 32);
#pragma unroll
            for (int ntp = 0; ntp < 4; ntp++) {
                unsigned h0, h1, h2, h3, l0, l1, l2, l3;
                ldsm4(h0, h1, h2, h3, bH + ntp * (16 * 20 * 4) + ks * 32);
                ldsm4(l0, l1, l2, l3, bL + ntp * (16 * 20 * 4) + ks * 32);
                mma_tf32(acc[0][2 * ntp + 0], a0, h0, h1);
                mma_tf32(acc[0][2 * ntp + 0], a0, l0, l1);
                mma_tf32(acc[0][2 * ntp + 1], a0, h2, h3);
                mma_tf32(acc[0][2 * ntp + 1], a0, l2, l3);
                mma_tf32(acc[1][2 * ntp + 0], a1, h0, h1);
                mma_tf32(acc[1][2 * ntp + 0], a1, l0, l1);
                mma_tf32(acc[1][2 * ntp + 1], a1, h2, h3);
                mma_tf32(acc[1][2 * ntp + 1], a1, l2, l3);
            }
        }
    }
#undef STAGE_ITER

#pragma unroll
    for (int mi = 0; mi < 2; mi++) {
        int r0 = m0 + 32 * wm + 16 * mi + g;
        int r1 = r0 + 8;
#pragma unroll
        for (int nt = 0; nt < 8; nt++) {
            int n = n0 + 64 * wn + 8 * nt + 2 * q;
            float2 b2 = *(const float2*)(bias + n);
            float2 v0, v1;
            v0.x = acc[mi][nt][0] + b2.x; v0.y = acc[mi][nt][1] + b2.y;
            v1.x = acc[mi][nt][2] + b2.x; v1.y = acc[mi][nt][3] + b2.y;
            if (mode == 1) {
                float sc = (n < CDIM) ? QSCALE : 1.0f;
                v0.x = f2tff(v0.x * sc); v0.y = f2tff(v0.y * sc);
                v1.x = f2tff(v1.x * sc); v1.y = f2tff(v1.y * sc);
            }
            *(float2*)(Y + (size_t)r0 * Nd + n) = v0;
            *(float2*)(Y + (size_t)r1 * Nd + n) = v1;
        }
    }
}

__global__ void __launch_bounds__(256, 2) k_gemm_qkv(const float* __restrict__ qb) {
    extern __shared__ float smg[];
    gemm_x2(g_x_tf, g_wq_hi, g_wq_lo, qb, g_qkv, C3, CDIM, 1, smg);
}
__global__ void __launch_bounds__(256, 2) k_gemm_proj(const float* __restrict__ pb,
                                                      float* __restrict__ out) {
    extern __shared__ float smg[];
    gemm_x2(g_att, g_pw_hi, g_pw_lo, pb, out, CDIM, CDIM, 0, smg);
}

// ---------------------------------------------------------------------------
// K: per-head V transpose with KEY PERMUTATION rho=[0,2,4,6,1,3,5,7].
// ---------------------------------------------------------------------------
__global__ void __launch_bounds__(256) k_vT() {
    __shared__ float t[128 * 68];
    int h = blockIdx.y, kb = blockIdx.x;
    int tid = threadIdx.x;
#pragma unroll
    for (int l = 0; l < 8; l++) {
        int c = tid + 256 * l;
        int key = c >> 4, dq = c & 15;
        *(float4*)(t + key * 68 + 4 * dq) =
            *(const float4*)(g_qkv + (size_t)(kb * 128 + key) * C3 + 2 * CDIM + h * HD + 4 * dq);
    }
    __syncthreads();
#pragma unroll
    for (int l = 0; l < 8; l++) {
        int c = tid + 256 * l;
        int d = c >> 5, kq = c & 31;
        float4 v;
#pragma unroll
        for (int i = 0; i < 4; i++) {
            int p = 4 * kq + i;
            int grp = p & ~7, r = p & 7;
            int key = (r < 4) ? grp + 2 * r : grp + 2 * (r - 4) + 1;
            ((float*)&v)[i] = t[key * 68 + d];
        }
        *(float4*)(g_vT + (size_t)(h * HD + d) * NTOK + kb * 128 + 4 * kq) = v;
    }
}

// ---------------------------------------------------------------------------
// Flash attention, tf32 MMA, fixed-max softmax, ex2 FUSED into the PV loop
// per-ks so MUFU overlaps tensor work (no tensor-idle softmax phase).
// smem: Ks[2][64*68] | Vt[2][64*68] | Ps[128*68]  (104448 B), 2 CTAs/SM.
// ---------------------------------------------------------------------------
#define FK 4352            // 64*68 floats
__global__ void __launch_bounds__(256, 2) k_flash() {
    extern __shared__ float sm[];
    float* Ks = sm;
    float* Vt = sm + 2 * FK;
    float* Ps = sm + 4 * FK;       // Q staging only

    int tid = threadIdx.x;
    int lane = tid & 31;
    int w = tid >> 5;
    int h = blockIdx.y;
    int q0 = blockIdx.x * 128;

    unsigned ksB = smem_u32(Ks), vtB = smem_u32(Vt), psB = smem_u32(Ps);
    const unsigned FKB = FK * 4;

#define STAGE_KV(kbx, bufx)                                                       \
    {                                                                             \
        int k0s = (kbx) * 64;                                                     \
        unsigned bo = (bufx) * FKB;                                               \
        _Pragma("unroll")                                                         \
        for (int l = 0; l < 4; l++) {                                             \
            int c = tid + 256 * l;                                                \
            int row = c >> 4, qd = c & 15;                                        \
            cpasync16(ksB + bo + ((row * 68 + 4 * qd) << 2),                      \
                      g_qkv + (size_t)(k0s + row) * C3 + CDIM + h * HD + 4 * qd); \
            cpasync16(vtB + bo + ((row * 68 + 4 * qd) << 2),                      \
                      g_vT + (size_t)(h * HD + row) * NTOK + k0s + 4 * qd);       \
        }                                                                         \
        asm volatile("cp.async.commit_group;");                                   \
    }

    // stage Q + KV0
#pragma unroll
    for (int l = 0; l < 8; l++) {
        int c = tid + 256 * l;
        int row = c >> 4, qd = c & 15;
        cpasync16(psB + ((row * 68 + 4 * qd) << 2),
                  g_qkv + (size_t)(q0 + row) * C3 + h * HD + 4 * qd);
    }
    STAGE_KV(0, 0)
    asm volatile("cp.async.wait_group 0;");
    __syncthreads();

    int roffA = ((lane >> 3) & 1) * 8 + (lane & 7);
    int coffA = (lane >> 4) * 4;
    unsigned aAddr = psB + (((16 * w + roffA) * 68 + coffA) << 2);
    unsigned qf[8][4];
#pragma unroll
    for (int ks = 0; ks < 8; ks++)
        ldsm4(qf[ks][0], qf[ks][1], qf[ks][2], qf[ks][3], aAddr + ks * 32);

    int roffB = ((lane >> 4) & 1) * 8 + (lane & 7);
    int coffB = ((lane >> 3) & 1) * 4;
    unsigned kAddr0 = ksB + ((roffB * 68 + coffB) << 2);
    unsigned vAddr0 = vtB + ((roffB * 68 + coffB) << 2);

    float o[8][4];
#pragma unroll
    for (int nt = 0; nt < 8; nt++)
#pragma unroll
        for (int e = 0; e < 4; e++) o[nt][e] = 0.f;
    float li0 = 0.f, li1 = 0.f;      // per-thread partial row sums

    for (int kb = 0; kb < NTOK / 64; kb++) {
        int buf = kb & 1;
        asm volatile("cp.async.wait_group 0;");
        __syncthreads();                 // stage(kb) visible; buf^1 readers done
        if (kb + 1 < NTOK / 64) STAGE_KV(kb + 1, buf ^ 1)

        // ---- S = Q K^T ----
        unsigned kAddr = kAddr0 + buf * FKB;
        float s[8][4];
#pragma unroll
        for (int nt = 0; nt < 8; nt++)
#pragma unroll
            for (int e = 0; e < 4; e++) s[nt][e] = 0.f;
#pragma unroll
        for (int ks = 0; ks < 8; ks++) {
#pragma unroll
            for (int ntp = 0; ntp < 4; ntp++) {
                unsigned b0, b1, b2, b3;
                ldsm4(b0, b1, b2, b3, kAddr + ntp * (16 * 68 * 4) + ks * 32);
                mma_tf32(s[2 * ntp + 0], qf[ks], b0, b1);
                mma_tf32(s[2 * ntp + 1], qf[ks], b2, b3);
            }
        }

        // ---- fused softmax + PV: per-ks ex2/cvt overlaps prior chunk's mma ----
        unsigned vAddr = vAddr0 + buf * FKB;
#pragma unroll
        for (int ks = 0; ks < 8; ks++) {
            float e0 = ex2f(s[ks][0]);
            float e1 = ex2f(s[ks][1]);
            float e2 = ex2f(s[ks][2]);
            float e3 = ex2f(s[ks][3]);
            li0 += e0 + e1;
            li1 += e2 + e3;
            unsigned pf[4];
            pf[0] = f2tf(e0);
            pf[1] = f2tf(e2);
            pf[2] = f2tf(e1);
            pf[3] = f2tf(e3);
#pragma unroll
            for (int ntp = 0; ntp < 4; ntp++) {
                unsigned b0, b1, b2, b3;
                ldsm4(b0, b1, b2, b3, vAddr + ntp * (16 * 68 * 4) + ks * 32);
                mma_tf32(o[2 * ntp + 0], pf, b0, b1);
                mma_tf32(o[2 * ntp + 1], pf, b2, b3);
            }
        }
    }
#undef STAGE_KV

    // ---- one-time row-sum reduction, normalize, writeback ----
    li0 += __shfl_xor_sync(0xffffffffu, li0, 1);
    li0 += __shfl_xor_sync(0xffffffffu, li0, 2);
    li1 += __shfl_xor_sync(0xffffffffu, li1, 1);
    li1 += __shfl_xor_sync(0xffffffffu, li1, 2);

    int g = lane >> 2, q = lane & 3;
    float inv0 = 1.f / li0;
    float inv1 = 1.f / li1;
    int r0 = q0 + 16 * w + g;
    int r1 = r0 + 8;
#pragma unroll
    for (int nt = 0; nt < 8; nt++) {
        int c = h * HD + 8 * nt + 2 * q;
        float2 v0; v0.x = f2tff(o[nt][0] * inv0); v0.y = f2tff(o[nt][1] * inv0);
        float2 v1; v1.x = f2tff(o[nt][2] * inv1); v1.y = f2tff(o[nt][3] * inv1);
        *(float2*)(g_att + (size_t)r0 * CDIM + c) = v0;
        *(float2*)(g_att + (size_t)r1 * CDIM + c) = v1;
    }
}

// ---------------------------------------------------------------------------
extern "C" void kernel_launch(void* const* d_in, const int* in_sizes, int n_in,
                              void* d_out, int out_size) {
    const float* x         = (const float*)d_in[0];
    const float* templates = (const float*)d_in[1];
    const float* coeffs    = (const float*)d_in[2];
    const float* qkv_bias  = (const float*)d_in[3];
    const float* proj_w    = (const float*)d_in[4];
    const float* proj_b    = (const float*)d_in[5];
    float* out = (float*)d_out;

    k_prologue<<<NB_W + NB_PW + NB_X, 256>>>(templates, coeffs, proj_w, x);

    int gsm = 6 * GTILE * (int)sizeof(float);   // 61440 B
    cudaFuncSetAttribute(k_gemm_qkv, cudaFuncAttributeMaxDynamicSharedMemorySize, gsm);
    cudaFuncSetAttribute(k_gemm_proj, cudaFuncAttributeMaxDynamicSharedMemorySize, gsm);

    k_gemm_qkv<<<dim3(C3 / 128, NTOK / 128), 256, gsm>>>(qkv_bias);

    k_vT<<<dim3(NTOK / 128, NH), 256>>>();

    int fsm = (4 * FK + 128 * 68) * (int)sizeof(float);  // 104448 B
    cudaFuncSetAttribute(k_flash, cudaFuncAttributeMaxDynamicSharedMemorySize, fsm);
    k_flash<<<dim3(NTOK / 128, NH), 256, fsm>>>();

    k_gemm_proj<<<dim3(CDIM / 128, NTOK / 128), 256, gsm>>>(proj_b, out);
}